// round 1
// baseline (speedup 1.0000x reference)
#include <cuda_runtime.h>
#include <cuda_bf16.h>
#include <math.h>

// ---------------------------------------------------------------------------
// Attention_69226282877525: BERT-style MHA
//   B=2, F=T=2048, HIDDEN=1024, N_HEADS=16, HEAD_DIM=64
// Inputs (metadata order):
//   0 from_tensor  [2,2048,1024] f32
//   1 to_tensor    [2,2048,1024] f32
//   2 attention_mask [2,2048,2048] i32
//   3 Wq [1024,1024]  4 bq [1024]
//   5 Wk [1024,1024]  6 bk [1024]
//   7 Wv [1024,1024]  8 bv [1024]
// Output: context [2,2048,1024] f32
// ---------------------------------------------------------------------------

#define BATCH   2
#define SEQ     2048
#define HIDDEN  1024
#define NHEADS  16
#define HDIM    64
#define MROWS   (BATCH * SEQ)      // 4096

// Scratch for Q/K/V in [B][N][S][H] layout (16 MB each).
__device__ float g_Qs[(size_t)BATCH * NHEADS * SEQ * HDIM];
__device__ float g_Ks[(size_t)BATCH * NHEADS * SEQ * HDIM];
__device__ float g_Vs[(size_t)BATCH * NHEADS * SEQ * HDIM];

// ---------------------------------------------------------------------------
// QKV projection GEMM: out[b][n][s][h] = X[b*S+s] . W[:, n*64+h] + bias
// 64x64 tiles, K-tile 16, 256 threads, 4x4 per thread.
// ---------------------------------------------------------------------------
__global__ void qkv_gemm_kernel(const float* __restrict__ X,
                                const float* __restrict__ W,
                                const float* __restrict__ bias,
                                float* __restrict__ out)
{
    __shared__ float sA[16][65];   // [k][m]
    __shared__ float sB[16][65];   // [k][n]

    const int tid = threadIdx.x;          // 256 threads
    const int tx = tid & 15;
    const int ty = tid >> 4;
    const int row0 = blockIdx.y * 64;
    const int col0 = blockIdx.x * 64;

    float acc[4][4] = {};

    for (int k0 = 0; k0 < HIDDEN; k0 += 16) {
        // Load A tile: 64 rows x 16 k  (coalesced along k)
        {
            const int c = tid & 15;
            const int r = tid >> 4;
            #pragma unroll
            for (int p = 0; p < 4; p++) {
                const int rr = r + p * 16;
                sA[c][rr] = X[(size_t)(row0 + rr) * HIDDEN + k0 + c];
            }
        }
        // Load B tile: 16 k x 64 n (coalesced along n)
        {
            const int c = tid & 63;
            const int r = tid >> 6;
            #pragma unroll
            for (int p = 0; p < 4; p++) {
                const int kk = r + p * 4;
                sB[kk][c] = W[(size_t)(k0 + kk) * HIDDEN + col0 + c];
            }
        }
        __syncthreads();

        #pragma unroll
        for (int kk = 0; kk < 16; kk++) {
            float a[4], b[4];
            #pragma unroll
            for (int i = 0; i < 4; i++) a[i] = sA[kk][ty * 4 + i];
            #pragma unroll
            for (int j = 0; j < 4; j++) b[j] = sB[kk][tx * 4 + j];
            #pragma unroll
            for (int i = 0; i < 4; i++)
                #pragma unroll
                for (int j = 0; j < 4; j++)
                    acc[i][j] += a[i] * b[j];
        }
        __syncthreads();
    }

    // Epilogue: bias + transpose-store to [B][N][S][H]
    #pragma unroll
    for (int i = 0; i < 4; i++) {
        const int row = row0 + ty * 4 + i;
        const int b = row / SEQ;
        const int s = row % SEQ;
        #pragma unroll
        for (int j = 0; j < 4; j++) {
            const int col = col0 + tx * 4 + j;
            const int n = col >> 6;
            const int h = col & 63;
            out[(((size_t)b * NHEADS + n) * SEQ + s) * HDIM + h] =
                acc[i][j] + bias[col];
        }
    }
}

// ---------------------------------------------------------------------------
// Flash attention: one CTA per (f-tile of 64, batch*head).
// S-tile 64x64 in SMEM, online softmax, O in registers (4x4/thread).
// ---------------------------------------------------------------------------
#define FL_SMEM (4 * 64 * 65 * 4 + 3 * 64 * 4)   // 67328 bytes

__global__ void flash_attn_kernel(const float* __restrict__ Q,
                                  const float* __restrict__ K,
                                  const float* __restrict__ V,
                                  const int* __restrict__ mask,
                                  float* __restrict__ out)
{
    extern __shared__ float sm[];
    float* qs   = sm;                 // [64][65]
    float* ks   = qs + 64 * 65;      // [64][65]
    float* vs   = ks + 64 * 65;      // [64][65]
    float* st   = vs + 64 * 65;      // [64][65] scores / probs
    float* rowm = st + 64 * 65;      // [64]
    float* rowl = rowm + 64;         // [64]
    float* rowa = rowl + 64;         // [64]

    const int tid = threadIdx.x;     // 256
    const int tx = tid & 15;
    const int ty = tid >> 4;

    const int bn = blockIdx.y;       // b*16 + n
    const int b  = bn >> 4;
    const int n  = bn & 15;
    const int f0 = blockIdx.x * 64;

    const float* Qb = Q + ((size_t)bn * SEQ + f0) * HDIM;
    const float* Kb = K + (size_t)bn * SEQ * HDIM;
    const float* Vb = V + (size_t)bn * SEQ * HDIM;
    const int*   Mb = mask + ((size_t)b * SEQ + f0) * SEQ;

    // Load Q tile (4096 floats, coalesced)
    for (int idx = tid; idx < 64 * 64; idx += 256) {
        const int r = idx >> 6, c = idx & 63;
        qs[r * 65 + c] = Qb[idx];
    }
    if (tid < 64) { rowm[tid] = -1e30f; rowl[tid] = 0.0f; }

    float O[4][4] = {};
    const float scale = 0.125f;   // 1/sqrt(64)

    __syncthreads();

    for (int t0 = 0; t0 < SEQ; t0 += 64) {
        // Load K/V tiles and mask adder (into st)
        for (int idx = tid; idx < 64 * 64; idx += 256) {
            const int r = idx >> 6, c = idx & 63;
            ks[r * 65 + c] = Kb[(size_t)(t0 + r) * HDIM + c];
            vs[r * 65 + c] = Vb[(size_t)(t0 + r) * HDIM + c];
            st[r * 65 + c] =
                -10000.0f * (1.0f - (float)Mb[(size_t)r * SEQ + t0 + c]);
        }
        __syncthreads();

        // S = scale * Q K^T + adder
        float accs[4][4] = {};
        #pragma unroll
        for (int h = 0; h < HDIM; h++) {
            float a[4], bb[4];
            #pragma unroll
            for (int i = 0; i < 4; i++) a[i]  = qs[(ty * 4 + i) * 65 + h];
            #pragma unroll
            for (int j = 0; j < 4; j++) bb[j] = ks[(tx * 4 + j) * 65 + h];
            #pragma unroll
            for (int i = 0; i < 4; i++)
                #pragma unroll
                for (int j = 0; j < 4; j++)
                    accs[i][j] += a[i] * bb[j];
        }
        #pragma unroll
        for (int i = 0; i < 4; i++)
            #pragma unroll
            for (int j = 0; j < 4; j++) {
                const int si = (ty * 4 + i) * 65 + tx * 4 + j;
                st[si] = accs[i][j] * scale + st[si];
            }
        __syncthreads();

        // Online softmax: 4 threads per row, 16 cols each.
        {
            const int row = tid >> 2;
            const int seg = tid & 3;
            float* srow = st + row * 65 + seg * 16;

            float lm = -1e30f;
            #pragma unroll
            for (int c = 0; c < 16; c++) lm = fmaxf(lm, srow[c]);
            lm = fmaxf(lm, __shfl_xor_sync(0xffffffffu, lm, 1));
            lm = fmaxf(lm, __shfl_xor_sync(0xffffffffu, lm, 2));

            const float mo = rowm[row];
            const float mn = fmaxf(mo, lm);

            float ls = 0.0f;
            #pragma unroll
            for (int c = 0; c < 16; c++) {
                const float p = __expf(srow[c] - mn);
                srow[c] = p;
                ls += p;
            }
            ls += __shfl_xor_sync(0xffffffffu, ls, 1);
            ls += __shfl_xor_sync(0xffffffffu, ls, 2);

            if (seg == 0) {
                const float alpha = __expf(mo - mn);
                rowa[row] = alpha;
                rowl[row] = rowl[row] * alpha + ls;
                rowm[row] = mn;
            }
        }
        __syncthreads();

        // Rescale O and accumulate O += P @ V
        {
            float al[4];
            #pragma unroll
            for (int i = 0; i < 4; i++) al[i] = rowa[ty * 4 + i];
            #pragma unroll
            for (int i = 0; i < 4; i++)
                #pragma unroll
                for (int j = 0; j < 4; j++) O[i][j] *= al[i];

            #pragma unroll
            for (int t = 0; t < 64; t++) {
                float p[4], vv[4];
                #pragma unroll
                for (int i = 0; i < 4; i++) p[i]  = st[(ty * 4 + i) * 65 + t];
                #pragma unroll
                for (int j = 0; j < 4; j++) vv[j] = vs[t * 65 + tx * 4 + j];
                #pragma unroll
                for (int i = 0; i < 4; i++)
                    #pragma unroll
                    for (int j = 0; j < 4; j++)
                        O[i][j] += p[i] * vv[j];
            }
        }
        __syncthreads();   // before next tile overwrites ks/vs/st
    }

    // Epilogue: normalize and store. out[b][f][n*64 + h]
    float linv[4];
    #pragma unroll
    for (int i = 0; i < 4; i++) linv[i] = 1.0f / rowl[ty * 4 + i];
    #pragma unroll
    for (int i = 0; i < 4; i++) {
        const size_t orow = ((size_t)b * SEQ + f0 + ty * 4 + i) * HIDDEN;
        #pragma unroll
        for (int j = 0; j < 4; j++) {
            out[orow + n * HDIM + tx * 4 + j] = O[i][j] * linv[i];
        }
    }
}

// ---------------------------------------------------------------------------
// kernel_launch
// ---------------------------------------------------------------------------
extern "C" void kernel_launch(void* const* d_in, const int* in_sizes, int n_in,
                              void* d_out, int out_size)
{
    (void)in_sizes; (void)n_in; (void)out_size;

    const float* from_t = (const float*)d_in[0];
    const float* to_t   = (const float*)d_in[1];
    const int*   msk    = (const int*)d_in[2];
    const float* Wq     = (const float*)d_in[3];
    const float* bq     = (const float*)d_in[4];
    const float* Wk     = (const float*)d_in[5];
    const float* bk     = (const float*)d_in[6];
    const float* Wv     = (const float*)d_in[7];
    const float* bv     = (const float*)d_in[8];
    float* out = (float*)d_out;

    float *qp, *kp, *vp;
    cudaGetSymbolAddress((void**)&qp, g_Qs);
    cudaGetSymbolAddress((void**)&kp, g_Ks);
    cudaGetSymbolAddress((void**)&vp, g_Vs);

    dim3 gg(HIDDEN / 64, MROWS / 64);   // (16, 64)
    qkv_gemm_kernel<<<gg, 256>>>(from_t, Wq, bq, qp);
    qkv_gemm_kernel<<<gg, 256>>>(to_t,   Wk, bk, kp);
    qkv_gemm_kernel<<<gg, 256>>>(to_t,   Wv, bv, vp);

    cudaFuncSetAttribute(flash_attn_kernel,
                         cudaFuncAttributeMaxDynamicSharedMemorySize, FL_SMEM);
    dim3 gf(SEQ / 64, BATCH * NHEADS);  // (32, 32)
    flash_attn_kernel<<<gf, 256, FL_SMEM>>>(qp, kp, vp, msk, out);
}

// round 2
// speedup vs baseline: 2.8699x; 2.8699x over previous
#include <cuda_runtime.h>
#include <cuda_bf16.h>
#include <math.h>

// ---------------------------------------------------------------------------
// Attention_69226282877525: BERT-style MHA on sm_103a, tf32 mma.sync path.
//   B=2, F=T=2048, HIDDEN=1024, N_HEADS=16, HEAD_DIM=64
// ---------------------------------------------------------------------------

#define BATCH   2
#define SEQ     2048
#define HIDDEN  1024
#define NHEADS  16
#define HDIM    64
#define MROWS   (BATCH * SEQ)      // 4096

// Scratch for Q/K/V in [B][N][S][H] layout (16 MB each).
__device__ float g_Qs[(size_t)BATCH * NHEADS * SEQ * HDIM];
__device__ float g_Ks[(size_t)BATCH * NHEADS * SEQ * HDIM];
__device__ float g_Vs[(size_t)BATCH * NHEADS * SEQ * HDIM];

// --------------------------- helpers ---------------------------------------
__device__ __forceinline__ unsigned f2tf(float x) {
    unsigned r;
    asm("cvt.rna.tf32.f32 %0, %1;" : "=r"(r) : "f"(x));
    return r;
}
__device__ __forceinline__ float f2tf_f(float x) {
    return __uint_as_float(f2tf(x));
}
__device__ __forceinline__ void cvt4(float4& v) {
    v.x = f2tf_f(v.x); v.y = f2tf_f(v.y); v.z = f2tf_f(v.z); v.w = f2tf_f(v.w);
}

__device__ __forceinline__ void mma_tf32(float c[4], const unsigned a[4],
                                         const unsigned b[2]) {
    asm volatile(
        "mma.sync.aligned.m16n8k8.row.col.f32.tf32.tf32.f32 "
        "{%0,%1,%2,%3}, {%4,%5,%6,%7}, {%8,%9}, {%0,%1,%2,%3};\n"
        : "+f"(c[0]), "+f"(c[1]), "+f"(c[2]), "+f"(c[3])
        : "r"(a[0]), "r"(a[1]), "r"(a[2]), "r"(a[3]), "r"(b[0]), "r"(b[1]));
}

// ---------------------------------------------------------------------------
// QKV projection GEMM (tf32 mma): out[b][n][s][h] = X . W + bias, transposed
// CTA 256 thr, tile 128x128, ktile 32, 8 warps (4 m x 2 n), warp tile 32x64.
// Double-buffered SMEM, register-staged global loads, 1 sync per k-tile.
// ---------------------------------------------------------------------------
#define GEMM_SMEM ((2 * 128 * 36 + 2 * 32 * 132) * 4)   // 70656 bytes

__global__ __launch_bounds__(256) void gemm_mma_kernel(
    const float* __restrict__ X, const float* __restrict__ W,
    const float* __restrict__ bias, float* __restrict__ out)
{
    extern __shared__ float smg[];
    float* As = smg;                    // [2][128][36]
    float* Bs = smg + 2 * 128 * 36;     // [2][32][132]

    const int tid  = threadIdx.x;
    const int w    = tid >> 5;
    const int lane = tid & 31;
    const int gid  = lane >> 2;
    const int tid4 = lane & 3;
    const int wm   = w & 3;             // 0..3
    const int wn   = w >> 2;            // 0..1
    const int row0 = blockIdx.y * 128;
    const int col0 = blockIdx.x * 128;

    float4 ar[4], br[4];

    // prologue: load k-tile 0
    #pragma unroll
    for (int i = 0; i < 4; i++) {
        const int idx = tid + i * 256;
        { const int r = idx >> 3, c4 = idx & 7;
          ar[i] = *(const float4*)(X + (size_t)(row0 + r) * HIDDEN + c4 * 4); }
        { const int r = idx >> 5, c4 = idx & 31;
          br[i] = *(const float4*)(W + (size_t)r * HIDDEN + col0 + c4 * 4); }
    }
    #pragma unroll
    for (int i = 0; i < 4; i++) {
        const int idx = tid + i * 256;
        cvt4(ar[i]); cvt4(br[i]);
        { const int r = idx >> 3, c4 = idx & 7;
          *(float4*)(As + r * 36 + c4 * 4) = ar[i]; }
        { const int r = idx >> 5, c4 = idx & 31;
          *(float4*)(Bs + r * 132 + c4 * 4) = br[i]; }
    }
    __syncthreads();

    float C[2][8][4] = {};

    for (int kt = 0; kt < 32; kt++) {
        const int buf = kt & 1;
        // prefetch next tile to registers
        if (kt < 31) {
            const int k0 = (kt + 1) * 32;
            #pragma unroll
            for (int i = 0; i < 4; i++) {
                const int idx = tid + i * 256;
                { const int r = idx >> 3, c4 = idx & 7;
                  ar[i] = *(const float4*)(X + (size_t)(row0 + r) * HIDDEN + k0 + c4 * 4); }
                { const int r = idx >> 5, c4 = idx & 31;
                  br[i] = *(const float4*)(W + (size_t)(k0 + r) * HIDDEN + col0 + c4 * 4); }
            }
        }
        // compute
        const float* Ab = As + buf * 128 * 36;
        const float* Bb = Bs + buf * 32 * 132;
        #pragma unroll
        for (int ks = 0; ks < 4; ks++) {
            unsigned a[2][4];
            #pragma unroll
            for (int mb = 0; mb < 2; mb++) {
                const int base = (wm * 32 + mb * 16 + gid) * 36 + ks * 8 + tid4;
                a[mb][0] = __float_as_uint(Ab[base]);
                a[mb][1] = __float_as_uint(Ab[base + 8 * 36]);
                a[mb][2] = __float_as_uint(Ab[base + 4]);
                a[mb][3] = __float_as_uint(Ab[base + 8 * 36 + 4]);
            }
            #pragma unroll
            for (int nb = 0; nb < 8; nb++) {
                unsigned bf[2];
                const int bbase = (ks * 8 + tid4) * 132 + wn * 64 + nb * 8 + gid;
                bf[0] = __float_as_uint(Bb[bbase]);
                bf[1] = __float_as_uint(Bb[bbase + 4 * 132]);
                mma_tf32(C[0][nb], a[0], bf);
                mma_tf32(C[1][nb], a[1], bf);
            }
        }
        // store next tile
        if (kt < 31) {
            float* An = As + ((kt + 1) & 1) * 128 * 36;
            float* Bn = Bs + ((kt + 1) & 1) * 32 * 132;
            #pragma unroll
            for (int i = 0; i < 4; i++) {
                const int idx = tid + i * 256;
                cvt4(ar[i]); cvt4(br[i]);
                { const int r = idx >> 3, c4 = idx & 7;
                  *(float4*)(An + r * 36 + c4 * 4) = ar[i]; }
                { const int r = idx >> 5, c4 = idx & 31;
                  *(float4*)(Bn + r * 132 + c4 * 4) = br[i]; }
            }
        }
        __syncthreads();
    }

    // epilogue: bias + transpose-store to [B][N][S][H]
    const int colbase = col0 + wn * 64;       // multiple of 64
    const int nhead   = colbase >> 6;
    #pragma unroll
    for (int mb = 0; mb < 2; mb++) {
        #pragma unroll
        for (int h = 0; h < 2; h++) {
            const int row = row0 + wm * 32 + mb * 16 + gid + 8 * h;
            const int b   = row >> 11;
            const int s   = row & 2047;
            float* op = out + (((size_t)b * NHEADS + nhead) * SEQ + s) * HDIM;
            #pragma unroll
            for (int nb = 0; nb < 8; nb++) {
                const int hh = nb * 8 + 2 * tid4;
                float2 v;
                v.x = C[mb][nb][2 * h]     + bias[colbase + hh];
                v.y = C[mb][nb][2 * h + 1] + bias[colbase + hh + 1];
                *(float2*)(op + hh) = v;
            }
        }
    }
}

// ---------------------------------------------------------------------------
// Flash attention with tf32 mma. CTA 128 thr (4 warps), f-tile 128
// (warp = 32 rows), T-tile 64. Q/K/V/P staged in SMEM as tf32.
// Mask read directly from global (int2, L2-resident).
// ---------------------------------------------------------------------------
#define ATT_SMEM ((128 * 68 + 64 * 68 + 64 * 68 + 4 * 32 * 68) * 4) // 104448

__global__ __launch_bounds__(128) void flash_mma_kernel(
    const float* __restrict__ Q, const float* __restrict__ K,
    const float* __restrict__ V, const int* __restrict__ mask,
    float* __restrict__ out)
{
    extern __shared__ float sm[];
    float* Qs = sm;                       // [128][68]
    float* Ks = Qs + 128 * 68;            // [64][68]
    float* Vs = Ks + 64 * 68;             // [64][68]
    float* Ps = Vs + 64 * 68;             // [4][32][68]

    const int tid  = threadIdx.x;
    const int w    = tid >> 5;
    const int lane = tid & 31;
    const int gid  = lane >> 2;
    const int tid4 = lane & 3;

    const int bn = blockIdx.y;            // b*16 + head
    const int b  = bn >> 4;
    const int nh = bn & 15;
    const int f0 = blockIdx.x * 128;

    const float* Qp = Q + ((size_t)bn * SEQ + f0) * HDIM;
    const float* Kp = K + (size_t)bn * SEQ * HDIM;
    const float* Vp = V + (size_t)bn * SEQ * HDIM;

    // stage Q tile (128x64), converted to tf32
    #pragma unroll
    for (int i = 0; i < 16; i++) {
        const int idx = tid + i * 128;    // float4 index
        const int r = idx >> 4, c4 = idx & 15;
        float4 v = *(const float4*)(Qp + (size_t)r * HDIM + c4 * 4);
        cvt4(v);
        *(float4*)(Qs + r * 68 + c4 * 4) = v;
    }

    float O[2][8][4] = {};
    float mrow[2][2] = {{-1e30f, -1e30f}, {-1e30f, -1e30f}};
    float lrow[2][2] = {};
    float* Pw = Ps + w * 32 * 68;

    for (int t0 = 0; t0 < SEQ; t0 += 64) {
        __syncthreads();   // protect Ks/Vs (also orders first Q staging)
        // stage K and V tiles (64x64 each) as tf32
        #pragma unroll
        for (int i = 0; i < 8; i++) {
            const int idx = tid + i * 128;
            const int r = idx >> 4, c4 = idx & 15;
            float4 kv = *(const float4*)(Kp + (size_t)(t0 + r) * HDIM + c4 * 4);
            float4 vv = *(const float4*)(Vp + (size_t)(t0 + r) * HDIM + c4 * 4);
            cvt4(kv); cvt4(vv);
            *(float4*)(Ks + r * 68 + c4 * 4) = kv;
            *(float4*)(Vs + r * 68 + c4 * 4) = vv;
        }
        __syncthreads();

        // ---- S = Q @ K^T ----
        float S[2][8][4] = {};
        #pragma unroll
        for (int ks = 0; ks < 8; ks++) {
            unsigned a[2][4];
            #pragma unroll
            for (int mb = 0; mb < 2; mb++) {
                const int base = (w * 32 + mb * 16 + gid) * 68 + ks * 8 + tid4;
                a[mb][0] = __float_as_uint(Qs[base]);
                a[mb][1] = __float_as_uint(Qs[base + 8 * 68]);
                a[mb][2] = __float_as_uint(Qs[base + 4]);
                a[mb][3] = __float_as_uint(Qs[base + 8 * 68 + 4]);
            }
            #pragma unroll
            for (int nb = 0; nb < 8; nb++) {
                unsigned bf[2];
                const int bbase = (nb * 8 + gid) * 68 + ks * 8 + tid4;
                bf[0] = __float_as_uint(Ks[bbase]);
                bf[1] = __float_as_uint(Ks[bbase + 4]);
                mma_tf32(S[0][nb], a[0], bf);
                mma_tf32(S[1][nb], a[1], bf);
            }
        }

        // ---- scale + mask + online softmax (registers) ----
        #pragma unroll
        for (int mb = 0; mb < 2; mb++) {
            #pragma unroll
            for (int h = 0; h < 2; h++) {
                const int rg = f0 + w * 32 + mb * 16 + gid + 8 * h;
                const int* mp = mask + ((size_t)b * SEQ + rg) * SEQ + t0 + 2 * tid4;
                float sv[8][2];
                float lm = -1e30f;
                #pragma unroll
                for (int nb = 0; nb < 8; nb++) {
                    const int2 mm = *(const int2*)(mp + nb * 8);
                    float s0 = S[mb][nb][2 * h]     * 0.125f + (float)(mm.x - 1) * 10000.0f;
                    float s1 = S[mb][nb][2 * h + 1] * 0.125f + (float)(mm.y - 1) * 10000.0f;
                    sv[nb][0] = s0; sv[nb][1] = s1;
                    lm = fmaxf(lm, fmaxf(s0, s1));
                }
                lm = fmaxf(lm, __shfl_xor_sync(0xffffffffu, lm, 1));
                lm = fmaxf(lm, __shfl_xor_sync(0xffffffffu, lm, 2));
                const float mo = mrow[mb][h];
                const float mn = fmaxf(mo, lm);
                const float al = __expf(mo - mn);
                mrow[mb][h] = mn;
                float ls = 0.0f;
                #pragma unroll
                for (int nb = 0; nb < 8; nb++) {
                    const float p0 = __expf(sv[nb][0] - mn);
                    const float p1 = __expf(sv[nb][1] - mn);
                    ls += p0 + p1;
                    S[mb][nb][2 * h] = p0;
                    S[mb][nb][2 * h + 1] = p1;
                }
                ls += __shfl_xor_sync(0xffffffffu, ls, 1);
                ls += __shfl_xor_sync(0xffffffffu, ls, 2);
                lrow[mb][h] = lrow[mb][h] * al + ls;
                #pragma unroll
                for (int nb = 0; nb < 8; nb++) {
                    O[mb][nb][2 * h]     *= al;
                    O[mb][nb][2 * h + 1] *= al;
                }
            }
        }

        // ---- write P (C-layout -> SMEM, tf32) ----
        __syncwarp();
        #pragma unroll
        for (int mb = 0; mb < 2; mb++)
            #pragma unroll
            for (int h = 0; h < 2; h++)
                #pragma unroll
                for (int nb = 0; nb < 8; nb++) {
                    float2 pv;
                    pv.x = f2tf_f(S[mb][nb][2 * h]);
                    pv.y = f2tf_f(S[mb][nb][2 * h + 1]);
                    *(float2*)(Pw + (mb * 16 + gid + 8 * h) * 68 + nb * 8 + 2 * tid4) = pv;
                }
        __syncwarp();

        // ---- O += P @ V ----
        #pragma unroll
        for (int kt = 0; kt < 8; kt++) {
            unsigned a[2][4];
            #pragma unroll
            for (int mb = 0; mb < 2; mb++) {
                const int base = (mb * 16 + gid) * 68 + kt * 8 + tid4;
                a[mb][0] = __float_as_uint(Pw[base]);
                a[mb][1] = __float_as_uint(Pw[base + 8 * 68]);
                a[mb][2] = __float_as_uint(Pw[base + 4]);
                a[mb][3] = __float_as_uint(Pw[base + 8 * 68 + 4]);
            }
            #pragma unroll
            for (int nb = 0; nb < 8; nb++) {
                unsigned bf[2];
                const int vbase = (kt * 8 + tid4) * 68 + nb * 8 + gid;
                bf[0] = __float_as_uint(Vs[vbase]);
                bf[1] = __float_as_uint(Vs[vbase + 4 * 68]);
                mma_tf32(O[0][nb], a[0], bf);
                mma_tf32(O[1][nb], a[1], bf);
            }
        }
    }

    // ---- epilogue: normalize and store ----
    #pragma unroll
    for (int mb = 0; mb < 2; mb++) {
        #pragma unroll
        for (int h = 0; h < 2; h++) {
            const float linv = 1.0f / lrow[mb][h];
            const int rg = f0 + w * 32 + mb * 16 + gid + 8 * h;
            float* op = out + ((size_t)b * SEQ + rg) * HIDDEN + nh * HDIM;
            #pragma unroll
            for (int nb = 0; nb < 8; nb++) {
                float2 v;
                v.x = O[mb][nb][2 * h] * linv;
                v.y = O[mb][nb][2 * h + 1] * linv;
                *(float2*)(op + nb * 8 + 2 * tid4) = v;
            }
        }
    }
}

// ---------------------------------------------------------------------------
// kernel_launch
// ---------------------------------------------------------------------------
extern "C" void kernel_launch(void* const* d_in, const int* in_sizes, int n_in,
                              void* d_out, int out_size)
{
    (void)in_sizes; (void)n_in; (void)out_size;

    const float* from_t = (const float*)d_in[0];
    const float* to_t   = (const float*)d_in[1];
    const int*   msk    = (const int*)d_in[2];
    const float* Wq     = (const float*)d_in[3];
    const float* bq     = (const float*)d_in[4];
    const float* Wk     = (const float*)d_in[5];
    const float* bk     = (const float*)d_in[6];
    const float* Wv     = (const float*)d_in[7];
    const float* bv     = (const float*)d_in[8];
    float* out = (float*)d_out;

    float *qp, *kp, *vp;
    cudaGetSymbolAddress((void**)&qp, g_Qs);
    cudaGetSymbolAddress((void**)&kp, g_Ks);
    cudaGetSymbolAddress((void**)&vp, g_Vs);

    cudaFuncSetAttribute(gemm_mma_kernel,
                         cudaFuncAttributeMaxDynamicSharedMemorySize, GEMM_SMEM);
    cudaFuncSetAttribute(flash_mma_kernel,
                         cudaFuncAttributeMaxDynamicSharedMemorySize, ATT_SMEM);

    dim3 gg(HIDDEN / 128, MROWS / 128);   // (8, 32)
    gemm_mma_kernel<<<gg, 256, GEMM_SMEM>>>(from_t, Wq, bq, qp);
    gemm_mma_kernel<<<gg, 256, GEMM_SMEM>>>(to_t,   Wk, bk, kp);
    gemm_mma_kernel<<<gg, 256, GEMM_SMEM>>>(to_t,   Wv, bv, vp);

    dim3 gf(SEQ / 128, BATCH * NHEADS);   // (16, 32)
    flash_mma_kernel<<<gf, 128, ATT_SMEM>>>(qp, kp, vp, msk, out);
}

// round 3
// speedup vs baseline: 3.1488x; 1.0972x over previous
#include <cuda_runtime.h>
#include <cuda_bf16.h>
#include <math.h>

// ---------------------------------------------------------------------------
// Attention_69226282877525: BERT-style MHA on sm_103a, tf32 mma.sync path.
//   B=2, F=T=2048, HIDDEN=1024, N_HEADS=16, HEAD_DIM=64
// ---------------------------------------------------------------------------

#define BATCH   2
#define SEQ     2048
#define HIDDEN  1024
#define NHEADS  16
#define HDIM    64
#define MROWS   (BATCH * SEQ)      // 4096

// Scratch for Q/K/V in [B][N][S][H] layout, tf32-pre-rounded fp32 (16 MB each)
__device__ float g_Qs[(size_t)BATCH * NHEADS * SEQ * HDIM];
__device__ float g_Ks[(size_t)BATCH * NHEADS * SEQ * HDIM];
__device__ float g_Vs[(size_t)BATCH * NHEADS * SEQ * HDIM];

// --------------------------- helpers ---------------------------------------
__device__ __forceinline__ unsigned f2tf(float x) {
    unsigned r;
    asm("cvt.rna.tf32.f32 %0, %1;" : "=r"(r) : "f"(x));
    return r;
}
__device__ __forceinline__ float f2tf_f(float x) {
    return __uint_as_float(f2tf(x));
}
__device__ __forceinline__ void cvt4(float4& v) {
    v.x = f2tf_f(v.x); v.y = f2tf_f(v.y); v.z = f2tf_f(v.z); v.w = f2tf_f(v.w);
}

__device__ __forceinline__ void mma_tf32(float c[4], const unsigned a[4],
                                         const unsigned b[2]) {
    asm volatile(
        "mma.sync.aligned.m16n8k8.row.col.f32.tf32.tf32.f32 "
        "{%0,%1,%2,%3}, {%4,%5,%6,%7}, {%8,%9}, {%0,%1,%2,%3};\n"
        : "+f"(c[0]), "+f"(c[1]), "+f"(c[2]), "+f"(c[3])
        : "r"(a[0]), "r"(a[1]), "r"(a[2]), "r"(a[3]), "r"(b[0]), "r"(b[1]));
}

__device__ __forceinline__ void cp_async16(float* dst_smem, const float* src) {
    unsigned d = (unsigned)__cvta_generic_to_shared(dst_smem);
    asm volatile("cp.async.cg.shared.global [%0], [%1], 16;" :: "r"(d), "l"(src));
}
__device__ __forceinline__ void cp_commit() {
    asm volatile("cp.async.commit_group;");
}
template<int N> __device__ __forceinline__ void cp_wait() {
    asm volatile("cp.async.wait_group %0;" :: "n"(N));
}

// ---------------------------------------------------------------------------
// Merged QKV projection GEMM (tf32 mma): blockIdx.z in {Q,K,V}.
// CTA 256 thr, tile 128x128, ktile 16, 8 warps (4m x 2n), warp tile 32x64.
// Double-buffered SMEM, register staging (16 regs), 1 sync per k-tile.
// Epilogue: bias add, tf32 rounding, transpose-store to [B][N][S][H].
// ---------------------------------------------------------------------------
#define GA_STR 20
#define GB_STR 136
#define GEMM_SMEM ((2 * 128 * GA_STR + 2 * 16 * GB_STR) * 4)   // 37888 bytes

__global__ __launch_bounds__(256, 2) void gemm_mma_kernel(
    const float* __restrict__ Xq, const float* __restrict__ Xkv,
    const float* __restrict__ Wq, const float* __restrict__ bq,
    const float* __restrict__ Wk, const float* __restrict__ bk,
    const float* __restrict__ Wv, const float* __restrict__ bv,
    float* __restrict__ oq, float* __restrict__ ok, float* __restrict__ ov)
{
    extern __shared__ float smg[];
    float* As = smg;                       // [2][128][GA_STR]
    float* Bs = smg + 2 * 128 * GA_STR;    // [2][16][GB_STR]

    const float* X; const float* W; const float* bias; float* out;
    if (blockIdx.z == 0)      { X = Xq;  W = Wq; bias = bq; out = oq; }
    else if (blockIdx.z == 1) { X = Xkv; W = Wk; bias = bk; out = ok; }
    else                      { X = Xkv; W = Wv; bias = bv; out = ov; }

    const int tid  = threadIdx.x;
    const int w    = tid >> 5;
    const int lane = tid & 31;
    const int gid  = lane >> 2;
    const int tid4 = lane & 3;
    const int wm   = w & 3;
    const int wn   = w >> 2;
    const int row0 = blockIdx.y * 128;
    const int col0 = blockIdx.x * 128;

    float4 ar[2], br[2];

    // prologue: k-tile 0
    #pragma unroll
    for (int i = 0; i < 2; i++) {
        const int idx = tid + i * 256;
        { const int r = idx >> 2, c4 = idx & 3;
          ar[i] = *(const float4*)(X + (size_t)(row0 + r) * HIDDEN + c4 * 4); }
        { const int r = idx >> 5, c4 = idx & 31;
          br[i] = *(const float4*)(W + (size_t)r * HIDDEN + col0 + c4 * 4); }
    }
    #pragma unroll
    for (int i = 0; i < 2; i++) {
        const int idx = tid + i * 256;
        cvt4(ar[i]); cvt4(br[i]);
        { const int r = idx >> 2, c4 = idx & 3;
          *(float4*)(As + r * GA_STR + c4 * 4) = ar[i]; }
        { const int r = idx >> 5, c4 = idx & 31;
          *(float4*)(Bs + r * GB_STR + c4 * 4) = br[i]; }
    }
    __syncthreads();

    float C[2][8][4] = {};

    for (int kt = 0; kt < 64; kt++) {
        const int buf = kt & 1;
        if (kt < 63) {
            const int k0 = (kt + 1) * 16;
            #pragma unroll
            for (int i = 0; i < 2; i++) {
                const int idx = tid + i * 256;
                { const int r = idx >> 2, c4 = idx & 3;
                  ar[i] = *(const float4*)(X + (size_t)(row0 + r) * HIDDEN + k0 + c4 * 4); }
                { const int r = idx >> 5, c4 = idx & 31;
                  br[i] = *(const float4*)(W + (size_t)(k0 + r) * HIDDEN + col0 + c4 * 4); }
            }
        }
        const float* Ab = As + buf * 128 * GA_STR;
        const float* Bb = Bs + buf * 16 * GB_STR;
        #pragma unroll
        for (int ks = 0; ks < 2; ks++) {
            unsigned a[2][4];
            #pragma unroll
            for (int mb = 0; mb < 2; mb++) {
                const int base = (wm * 32 + mb * 16 + gid) * GA_STR + ks * 8 + tid4;
                a[mb][0] = __float_as_uint(Ab[base]);
                a[mb][1] = __float_as_uint(Ab[base + 8 * GA_STR]);
                a[mb][2] = __float_as_uint(Ab[base + 4]);
                a[mb][3] = __float_as_uint(Ab[base + 8 * GA_STR + 4]);
            }
            #pragma unroll
            for (int nb = 0; nb < 8; nb++) {
                unsigned bf[2];
                const int bbase = (ks * 8 + tid4) * GB_STR + wn * 64 + nb * 8 + gid;
                bf[0] = __float_as_uint(Bb[bbase]);
                bf[1] = __float_as_uint(Bb[bbase + 4 * GB_STR]);
                mma_tf32(C[0][nb], a[0], bf);
                mma_tf32(C[1][nb], a[1], bf);
            }
        }
        if (kt < 63) {
            float* An = As + ((kt + 1) & 1) * 128 * GA_STR;
            float* Bn = Bs + ((kt + 1) & 1) * 16 * GB_STR;
            #pragma unroll
            for (int i = 0; i < 2; i++) {
                const int idx = tid + i * 256;
                cvt4(ar[i]); cvt4(br[i]);
                { const int r = idx >> 2, c4 = idx & 3;
                  *(float4*)(An + r * GA_STR + c4 * 4) = ar[i]; }
                { const int r = idx >> 5, c4 = idx & 31;
                  *(float4*)(Bn + r * GB_STR + c4 * 4) = br[i]; }
            }
        }
        __syncthreads();
    }

    // epilogue: bias + tf32 round + transpose-store to [B][N][S][H]
    const int colbase = col0 + wn * 64;       // multiple of 64
    const int nhead   = colbase >> 6;
    #pragma unroll
    for (int mb = 0; mb < 2; mb++) {
        #pragma unroll
        for (int h = 0; h < 2; h++) {
            const int row = row0 + wm * 32 + mb * 16 + gid + 8 * h;
            const int b   = row >> 11;
            const int s   = row & 2047;
            float* op = out + (((size_t)b * NHEADS + nhead) * SEQ + s) * HDIM;
            #pragma unroll
            for (int nb = 0; nb < 8; nb++) {
                const int hh = nb * 8 + 2 * tid4;
                float2 v;
                v.x = f2tf_f(C[mb][nb][2 * h]     + bias[colbase + hh]);
                v.y = f2tf_f(C[mb][nb][2 * h + 1] + bias[colbase + hh + 1]);
                *(float2*)(op + hh) = v;
            }
        }
    }
}

// ---------------------------------------------------------------------------
// Flash attention (tf32 mma): CTA 128 thr (4 warps x 32 rows), f-tile 128,
// T-tile 64. Q/K/V pre-rounded tf32 -> cp.async staging, no cvt.
// P transposed C-frag -> A-frag via shuffles (no SMEM round trip).
// SMEM 70656 B -> 3 CTAs/SM.
// ---------------------------------------------------------------------------
#define FQ_STR 68
#define FK_STR 68
#define FV_STR 72
#define ATT_SMEM ((128 * FQ_STR + 64 * FK_STR + 64 * FV_STR) * 4)  // 70656

__global__ __launch_bounds__(128, 3) void flash_mma_kernel(
    const float* __restrict__ Q, const float* __restrict__ K,
    const float* __restrict__ V, const int* __restrict__ mask,
    float* __restrict__ out)
{
    extern __shared__ float sm[];
    float* Qs = sm;                       // [128][68]
    float* Ks = Qs + 128 * FQ_STR;        // [64][68]
    float* Vs = Ks + 64 * FK_STR;         // [64][72]

    const int tid  = threadIdx.x;
    const int w    = tid >> 5;
    const int lane = tid & 31;
    const int gid  = lane >> 2;
    const int tid4 = lane & 3;

    const int bn = blockIdx.y;            // b*16 + head
    const int b  = bn >> 4;
    const int nh = bn & 15;
    const int f0 = blockIdx.x * 128;

    const float* Qp = Q + ((size_t)bn * SEQ + f0) * HDIM;
    const float* Kp = K + (size_t)bn * SEQ * HDIM;
    const float* Vp = V + (size_t)bn * SEQ * HDIM;

    // prologue: stage Q (128x64) + K0 + V0 via cp.async
    #pragma unroll
    for (int i = 0; i < 16; i++) {
        const int idx = tid + i * 128;
        const int r = idx >> 4, c = idx & 15;
        cp_async16(Qs + r * FQ_STR + c * 4, Qp + (size_t)r * HDIM + c * 4);
    }
    #pragma unroll
    for (int i = 0; i < 8; i++) {
        const int idx = tid + i * 128;
        const int r = idx >> 4, c = idx & 15;
        cp_async16(Ks + r * FK_STR + c * 4, Kp + (size_t)r * HDIM + c * 4);
        cp_async16(Vs + r * FV_STR + c * 4, Vp + (size_t)r * HDIM + c * 4);
    }
    cp_commit();

    float O[2][8][4] = {};
    float mrow[2][2] = {{-1e30f, -1e30f}, {-1e30f, -1e30f}};
    float lrow[2][2] = {};

    for (int t0 = 0; t0 < SEQ; t0 += 64) {
        cp_wait<0>();
        __syncthreads();

        // ---- S = Q @ K^T ----
        float S[2][8][4] = {};
        #pragma unroll
        for (int ks = 0; ks < 8; ks++) {
            unsigned a[2][4];
            #pragma unroll
            for (int mb = 0; mb < 2; mb++) {
                const int base = (w * 32 + mb * 16 + gid) * FQ_STR + ks * 8 + tid4;
                a[mb][0] = __float_as_uint(Qs[base]);
                a[mb][1] = __float_as_uint(Qs[base + 8 * FQ_STR]);
                a[mb][2] = __float_as_uint(Qs[base + 4]);
                a[mb][3] = __float_as_uint(Qs[base + 8 * FQ_STR + 4]);
            }
            #pragma unroll
            for (int nb = 0; nb < 8; nb++) {
                unsigned bf[2];
                const int bbase = (nb * 8 + gid) * FK_STR + ks * 8 + tid4;
                bf[0] = __float_as_uint(Ks[bbase]);
                bf[1] = __float_as_uint(Ks[bbase + 4]);
                mma_tf32(S[0][nb], a[0], bf);
                mma_tf32(S[1][nb], a[1], bf);
            }
        }
        __syncthreads();                  // all warps done with K tile

        // prefetch next K tile (overlaps softmax + PV)
        if (t0 + 64 < SEQ) {
            #pragma unroll
            for (int i = 0; i < 8; i++) {
                const int idx = tid + i * 128;
                const int r = idx >> 4, c = idx & 15;
                cp_async16(Ks + r * FK_STR + c * 4,
                           Kp + (size_t)(t0 + 64 + r) * HDIM + c * 4);
            }
            cp_commit();
        }

        // ---- scale + mask + online softmax (registers) ----
        #pragma unroll
        for (int mb = 0; mb < 2; mb++) {
            #pragma unroll
            for (int h = 0; h < 2; h++) {
                const int rg = f0 + w * 32 + mb * 16 + gid + 8 * h;
                const int* mp = mask + ((size_t)b * SEQ + rg) * SEQ + t0 + 2 * tid4;
                float sv[8][2];
                float lm = -1e30f;
                #pragma unroll
                for (int nb = 0; nb < 8; nb++) {
                    const int2 mm = *(const int2*)(mp + nb * 8);
                    float s0 = S[mb][nb][2 * h]     * 0.125f + (float)(mm.x - 1) * 10000.0f;
                    float s1 = S[mb][nb][2 * h + 1] * 0.125f + (float)(mm.y - 1) * 10000.0f;
                    sv[nb][0] = s0; sv[nb][1] = s1;
                    lm = fmaxf(lm, fmaxf(s0, s1));
                }
                lm = fmaxf(lm, __shfl_xor_sync(0xffffffffu, lm, 1));
                lm = fmaxf(lm, __shfl_xor_sync(0xffffffffu, lm, 2));
                const float mo = mrow[mb][h];
                const float mn = fmaxf(mo, lm);
                const float al = __expf(mo - mn);
                mrow[mb][h] = mn;
                float ls = 0.0f;
                #pragma unroll
                for (int nb = 0; nb < 8; nb++) {
                    const float p0 = __expf(sv[nb][0] - mn);
                    const float p1 = __expf(sv[nb][1] - mn);
                    ls += p0 + p1;
                    S[mb][nb][2 * h] = p0;
                    S[mb][nb][2 * h + 1] = p1;
                }
                ls += __shfl_xor_sync(0xffffffffu, ls, 1);
                ls += __shfl_xor_sync(0xffffffffu, ls, 2);
                lrow[mb][h] = lrow[mb][h] * al + ls;
                #pragma unroll
                for (int nb = 0; nb < 8; nb++) {
                    O[mb][nb][2 * h]     *= al;
                    O[mb][nb][2 * h + 1] *= al;
                }
            }
        }

        // ---- O += P @ V : shuffle-transpose P C-frag -> A-frag per k-block ----
        const int src0 = (lane & 28) | (tid4 >> 1);
        const int src1 = src0 + 2;
        const bool odd = (tid4 & 1);
        #pragma unroll
        for (int kt = 0; kt < 8; kt++) {
            unsigned a[2][4];
            #pragma unroll
            for (int mb = 0; mb < 2; mb++) {
                float e0 = __shfl_sync(0xffffffffu, S[mb][kt][0], src0);
                float o0 = __shfl_sync(0xffffffffu, S[mb][kt][1], src0);
                float e1 = __shfl_sync(0xffffffffu, S[mb][kt][0], src1);
                float o1 = __shfl_sync(0xffffffffu, S[mb][kt][1], src1);
                float e2 = __shfl_sync(0xffffffffu, S[mb][kt][2], src0);
                float o2 = __shfl_sync(0xffffffffu, S[mb][kt][3], src0);
                float e3 = __shfl_sync(0xffffffffu, S[mb][kt][2], src1);
                float o3 = __shfl_sync(0xffffffffu, S[mb][kt][3], src1);
                a[mb][0] = f2tf(odd ? o0 : e0);
                a[mb][1] = f2tf(odd ? o2 : e2);
                a[mb][2] = f2tf(odd ? o1 : e1);
                a[mb][3] = f2tf(odd ? o3 : e3);
            }
            #pragma unroll
            for (int nb = 0; nb < 8; nb++) {
                unsigned bf[2];
                const int vbase = (kt * 8 + tid4) * FV_STR + nb * 8 + gid;
                bf[0] = __float_as_uint(Vs[vbase]);
                bf[1] = __float_as_uint(Vs[vbase + 4 * FV_STR]);
                mma_tf32(O[0][nb], a[0], bf);
                mma_tf32(O[1][nb], a[1], bf);
            }
        }
        __syncthreads();                  // all warps done with V tile

        // prefetch next V tile
        if (t0 + 64 < SEQ) {
            #pragma unroll
            for (int i = 0; i < 8; i++) {
                const int idx = tid + i * 128;
                const int r = idx >> 4, c = idx & 15;
                cp_async16(Vs + r * FV_STR + c * 4,
                           Vp + (size_t)(t0 + 64 + r) * HDIM + c * 4);
            }
            cp_commit();
        }
    }

    // ---- epilogue: normalize and store ----
    #pragma unroll
    for (int mb = 0; mb < 2; mb++) {
        #pragma unroll
        for (int h = 0; h < 2; h++) {
            const float linv = 1.0f / lrow[mb][h];
            const int rg = f0 + w * 32 + mb * 16 + gid + 8 * h;
            float* op = out + ((size_t)b * SEQ + rg) * HIDDEN + nh * HDIM;
            #pragma unroll
            for (int nb = 0; nb < 8; nb++) {
                float2 v;
                v.x = O[mb][nb][2 * h] * linv;
                v.y = O[mb][nb][2 * h + 1] * linv;
                *(float2*)(op + nb * 8 + 2 * tid4) = v;
            }
        }
    }
}

// ---------------------------------------------------------------------------
// kernel_launch
// ---------------------------------------------------------------------------
extern "C" void kernel_launch(void* const* d_in, const int* in_sizes, int n_in,
                              void* d_out, int out_size)
{
    (void)in_sizes; (void)n_in; (void)out_size;

    const float* from_t = (const float*)d_in[0];
    const float* to_t   = (const float*)d_in[1];
    const int*   msk    = (const int*)d_in[2];
    const float* Wq     = (const float*)d_in[3];
    const float* bq     = (const float*)d_in[4];
    const float* Wk     = (const float*)d_in[5];
    const float* bk     = (const float*)d_in[6];
    const float* Wv     = (const float*)d_in[7];
    const float* bv     = (const float*)d_in[8];
    float* out = (float*)d_out;

    float *qp, *kp, *vp;
    cudaGetSymbolAddress((void**)&qp, g_Qs);
    cudaGetSymbolAddress((void**)&kp, g_Ks);
    cudaGetSymbolAddress((void**)&vp, g_Vs);

    cudaFuncSetAttribute(gemm_mma_kernel,
                         cudaFuncAttributeMaxDynamicSharedMemorySize, GEMM_SMEM);
    cudaFuncSetAttribute(flash_mma_kernel,
                         cudaFuncAttributeMaxDynamicSharedMemorySize, ATT_SMEM);

    dim3 gg(HIDDEN / 128, MROWS / 128, 3);   // (8, 32, 3)
    gemm_mma_kernel<<<gg, 256, GEMM_SMEM>>>(from_t, to_t, Wq, bq, Wk, bk,
                                            Wv, bv, qp, kp, vp);

    dim3 gf(SEQ / 128, BATCH * NHEADS);      // (16, 32)
    flash_mma_kernel<<<gf, 128, ATT_SMEM>>>(qp, kp, vp, msk, out);
}

// round 4
// speedup vs baseline: 3.7845x; 1.2019x over previous
#include <cuda_runtime.h>
#include <cuda_bf16.h>
#include <math.h>

// ---------------------------------------------------------------------------
// Attention_69226282877525: BERT-style MHA on sm_103a, tf32 mma.sync path.
//   B=2, F=T=2048, HIDDEN=1024, N_HEADS=16, HEAD_DIM=64
// ---------------------------------------------------------------------------

#define BATCH   2
#define SEQ     2048
#define HIDDEN  1024
#define NHEADS  16
#define HDIM    64
#define MROWS   (BATCH * SEQ)      // 4096

// Scratch for Q/K/V in [B][N][S][H] layout, tf32-pre-rounded fp32 (16 MB each)
__device__ float g_Qs[(size_t)BATCH * NHEADS * SEQ * HDIM];
__device__ float g_Ks[(size_t)BATCH * NHEADS * SEQ * HDIM];
__device__ float g_Vs[(size_t)BATCH * NHEADS * SEQ * HDIM];
// Packed attention mask bits: [B][F][T/32] (1 MB)
__device__ unsigned g_Mbits[(size_t)BATCH * SEQ * (SEQ / 32)];

// --------------------------- helpers ---------------------------------------
__device__ __forceinline__ unsigned f2tf(float x) {
    unsigned r;
    asm("cvt.rna.tf32.f32 %0, %1;" : "=r"(r) : "f"(x));
    return r;
}
__device__ __forceinline__ float f2tf_f(float x) {
    return __uint_as_float(f2tf(x));
}
__device__ __forceinline__ void cvt4(float4& v) {
    v.x = f2tf_f(v.x); v.y = f2tf_f(v.y); v.z = f2tf_f(v.z); v.w = f2tf_f(v.w);
}

__device__ __forceinline__ void mma_tf32(float c[4], const unsigned a[4],
                                         const unsigned b[2]) {
    asm volatile(
        "mma.sync.aligned.m16n8k8.row.col.f32.tf32.tf32.f32 "
        "{%0,%1,%2,%3}, {%4,%5,%6,%7}, {%8,%9}, {%0,%1,%2,%3};\n"
        : "+f"(c[0]), "+f"(c[1]), "+f"(c[2]), "+f"(c[3])
        : "r"(a[0]), "r"(a[1]), "r"(a[2]), "r"(a[3]), "r"(b[0]), "r"(b[1]));
}

__device__ __forceinline__ void cp_async16(float* dst_smem, const float* src) {
    unsigned d = (unsigned)__cvta_generic_to_shared(dst_smem);
    asm volatile("cp.async.cg.shared.global [%0], [%1], 16;" :: "r"(d), "l"(src));
}
__device__ __forceinline__ void cp_commit() {
    asm volatile("cp.async.commit_group;");
}
template<int N> __device__ __forceinline__ void cp_wait() {
    asm volatile("cp.async.wait_group %0;" :: "n"(N));
}

// ---------------------------------------------------------------------------
// Pack mask [B,F,T] int32 -> bitmask [B,F,T/32]. One warp per (b,f) row.
// ---------------------------------------------------------------------------
__global__ __launch_bounds__(256) void mask_bits_kernel(
    const int* __restrict__ mask, unsigned* __restrict__ bits)
{
    const int gw   = (blockIdx.x * 256 + threadIdx.x) >> 5;   // row index
    const int lane = threadIdx.x & 31;
    if (gw >= BATCH * SEQ) return;
    const int* mp = mask + (size_t)gw * SEQ;
    unsigned* bp  = bits + (size_t)gw * (SEQ / 32);
    #pragma unroll 4
    for (int c = 0; c < SEQ / 32; c++) {
        const int v = mp[c * 32 + lane];
        const unsigned w = __ballot_sync(0xffffffffu, v != 0);
        if (lane == 0) bp[c] = w;
    }
}

// ---------------------------------------------------------------------------
// Merged QKV projection GEMM (tf32 mma): blockIdx.z in {Q,K,V}.
// CTA 256 thr, tile 128x128, ktile 16, 8 warps (4m x 2n), warp tile 32x64.
// ---------------------------------------------------------------------------
#define GA_STR 20
#define GB_STR 136
#define GEMM_SMEM ((2 * 128 * GA_STR + 2 * 16 * GB_STR) * 4)   // 37888 bytes

__global__ __launch_bounds__(256, 2) void gemm_mma_kernel(
    const float* __restrict__ Xq, const float* __restrict__ Xkv,
    const float* __restrict__ Wq, const float* __restrict__ bq,
    const float* __restrict__ Wk, const float* __restrict__ bk,
    const float* __restrict__ Wv, const float* __restrict__ bv,
    float* __restrict__ oq, float* __restrict__ ok, float* __restrict__ ov)
{
    extern __shared__ float smg[];
    float* As = smg;                       // [2][128][GA_STR]
    float* Bs = smg + 2 * 128 * GA_STR;    // [2][16][GB_STR]

    const float* X; const float* W; const float* bias; float* out;
    if (blockIdx.z == 0)      { X = Xq;  W = Wq; bias = bq; out = oq; }
    else if (blockIdx.z == 1) { X = Xkv; W = Wk; bias = bk; out = ok; }
    else                      { X = Xkv; W = Wv; bias = bv; out = ov; }

    const int tid  = threadIdx.x;
    const int w    = tid >> 5;
    const int lane = tid & 31;
    const int gid  = lane >> 2;
    const int tid4 = lane & 3;
    const int wm   = w & 3;
    const int wn   = w >> 2;
    const int row0 = blockIdx.y * 128;
    const int col0 = blockIdx.x * 128;

    float4 ar[2], br[2];

    #pragma unroll
    for (int i = 0; i < 2; i++) {
        const int idx = tid + i * 256;
        { const int r = idx >> 2, c4 = idx & 3;
          ar[i] = *(const float4*)(X + (size_t)(row0 + r) * HIDDEN + c4 * 4); }
        { const int r = idx >> 5, c4 = idx & 31;
          br[i] = *(const float4*)(W + (size_t)r * HIDDEN + col0 + c4 * 4); }
    }
    #pragma unroll
    for (int i = 0; i < 2; i++) {
        const int idx = tid + i * 256;
        cvt4(ar[i]); cvt4(br[i]);
        { const int r = idx >> 2, c4 = idx & 3;
          *(float4*)(As + r * GA_STR + c4 * 4) = ar[i]; }
        { const int r = idx >> 5, c4 = idx & 31;
          *(float4*)(Bs + r * GB_STR + c4 * 4) = br[i]; }
    }
    __syncthreads();

    float C[2][8][4] = {};

    for (int kt = 0; kt < 64; kt++) {
        const int buf = kt & 1;
        if (kt < 63) {
            const int k0 = (kt + 1) * 16;
            #pragma unroll
            for (int i = 0; i < 2; i++) {
                const int idx = tid + i * 256;
                { const int r = idx >> 2, c4 = idx & 3;
                  ar[i] = *(const float4*)(X + (size_t)(row0 + r) * HIDDEN + k0 + c4 * 4); }
                { const int r = idx >> 5, c4 = idx & 31;
                  br[i] = *(const float4*)(W + (size_t)(k0 + r) * HIDDEN + col0 + c4 * 4); }
            }
        }
        const float* Ab = As + buf * 128 * GA_STR;
        const float* Bb = Bs + buf * 16 * GB_STR;
        #pragma unroll
        for (int ks = 0; ks < 2; ks++) {
            unsigned a[2][4];
            #pragma unroll
            for (int mb = 0; mb < 2; mb++) {
                const int base = (wm * 32 + mb * 16 + gid) * GA_STR + ks * 8 + tid4;
                a[mb][0] = __float_as_uint(Ab[base]);
                a[mb][1] = __float_as_uint(Ab[base + 8 * GA_STR]);
                a[mb][2] = __float_as_uint(Ab[base + 4]);
                a[mb][3] = __float_as_uint(Ab[base + 8 * GA_STR + 4]);
            }
            #pragma unroll
            for (int nb = 0; nb < 8; nb++) {
                unsigned bf[2];
                const int bbase = (ks * 8 + tid4) * GB_STR + wn * 64 + nb * 8 + gid;
                bf[0] = __float_as_uint(Bb[bbase]);
                bf[1] = __float_as_uint(Bb[bbase + 4 * GB_STR]);
                mma_tf32(C[0][nb], a[0], bf);
                mma_tf32(C[1][nb], a[1], bf);
            }
        }
        if (kt < 63) {
            float* An = As + ((kt + 1) & 1) * 128 * GA_STR;
            float* Bn = Bs + ((kt + 1) & 1) * 16 * GB_STR;
            #pragma unroll
            for (int i = 0; i < 2; i++) {
                const int idx = tid + i * 256;
                cvt4(ar[i]); cvt4(br[i]);
                { const int r = idx >> 2, c4 = idx & 3;
                  *(float4*)(An + r * GA_STR + c4 * 4) = ar[i]; }
                { const int r = idx >> 5, c4 = idx & 31;
                  *(float4*)(Bn + r * GB_STR + c4 * 4) = br[i]; }
            }
        }
        __syncthreads();
    }

    // epilogue: bias + tf32 round + transpose-store to [B][N][S][H]
    const int colbase = col0 + wn * 64;
    const int nhead   = colbase >> 6;
    #pragma unroll
    for (int mb = 0; mb < 2; mb++) {
        #pragma unroll
        for (int h = 0; h < 2; h++) {
            const int row = row0 + wm * 32 + mb * 16 + gid + 8 * h;
            const int b   = row >> 11;
            const int s   = row & 2047;
            float* op = out + (((size_t)b * NHEADS + nhead) * SEQ + s) * HDIM;
            #pragma unroll
            for (int nb = 0; nb < 8; nb++) {
                const int hh = nb * 8 + 2 * tid4;
                float2 v;
                v.x = f2tf_f(C[mb][nb][2 * h]     + bias[colbase + hh]);
                v.y = f2tf_f(C[mb][nb][2 * h + 1] + bias[colbase + hh + 1]);
                *(float2*)(op + hh) = v;
            }
        }
    }
}

// ---------------------------------------------------------------------------
// Flash attention (tf32 mma): CTA 128 thr (4 warps x 32 rows), f-tile 128,
// T-tile 64. Q/K/V pre-rounded tf32 via cp.async; split K/V wait groups;
// mask via packed bits (4 LDG.64 per tile, prefetched before QK).
// ---------------------------------------------------------------------------
#define FQ_STR 68
#define FK_STR 68
#define FV_STR 72
#define ATT_SMEM ((128 * FQ_STR + 64 * FK_STR + 64 * FV_STR) * 4)  // 70656

__global__ __launch_bounds__(128, 3) void flash_mma_kernel(
    const float* __restrict__ Q, const float* __restrict__ K,
    const float* __restrict__ V, const unsigned* __restrict__ mbitsg,
    float* __restrict__ out)
{
    extern __shared__ float sm[];
    float* Qs = sm;                       // [128][68]
    float* Ks = Qs + 128 * FQ_STR;        // [64][68]
    float* Vs = Ks + 64 * FK_STR;         // [64][72]

    const int tid  = threadIdx.x;
    const int w    = tid >> 5;
    const int lane = tid & 31;
    const int gid  = lane >> 2;
    const int tid4 = lane & 3;

    const int bn = blockIdx.y;            // b*16 + head
    const int b  = bn >> 4;
    const int nh = bn & 15;
    const int f0 = blockIdx.x * 128;

    const float* Qp = Q + ((size_t)bn * SEQ + f0) * HDIM;
    const float* Kp = K + (size_t)bn * SEQ * HDIM;
    const float* Vp = V + (size_t)bn * SEQ * HDIM;
    const unsigned* Mb = mbitsg + (size_t)b * SEQ * (SEQ / 32);

    // prologue: stage Q + K0 (group A), V0 (group B)
    #pragma unroll
    for (int i = 0; i < 16; i++) {
        const int idx = tid + i * 128;
        const int r = idx >> 4, c = idx & 15;
        cp_async16(Qs + r * FQ_STR + c * 4, Qp + (size_t)r * HDIM + c * 4);
    }
    #pragma unroll
    for (int i = 0; i < 8; i++) {
        const int idx = tid + i * 128;
        const int r = idx >> 4, c = idx & 15;
        cp_async16(Ks + r * FK_STR + c * 4, Kp + (size_t)r * HDIM + c * 4);
    }
    cp_commit();
    #pragma unroll
    for (int i = 0; i < 8; i++) {
        const int idx = tid + i * 128;
        const int r = idx >> 4, c = idx & 15;
        cp_async16(Vs + r * FV_STR + c * 4, Vp + (size_t)r * HDIM + c * 4);
    }
    cp_commit();

    float O[2][8][4] = {};
    float mrow[2][2] = {{-1e30f, -1e30f}, {-1e30f, -1e30f}};
    float lrow[2][2] = {};

    for (int t0 = 0; t0 < SEQ; t0 += 64) {
        cp_wait<1>();          // K(t) ready (V(t) may still be in flight)
        __syncthreads();

        // prefetch mask bits for this tile (hidden behind QK mma)
        unsigned long long mbits[2][2];
        #pragma unroll
        for (int mb = 0; mb < 2; mb++)
            #pragma unroll
            for (int h = 0; h < 2; h++) {
                const int rg = f0 + w * 32 + mb * 16 + gid + 8 * h;
                const uint2 mm = *(const uint2*)(Mb + (size_t)rg * (SEQ / 32) + (t0 >> 5));
                mbits[mb][h] = (unsigned long long)mm.x |
                               ((unsigned long long)mm.y << 32);
            }

        // ---- S = Q @ K^T ----
        float S[2][8][4] = {};
        #pragma unroll
        for (int ks = 0; ks < 8; ks++) {
            unsigned a[2][4];
            #pragma unroll
            for (int mb = 0; mb < 2; mb++) {
                const int base = (w * 32 + mb * 16 + gid) * FQ_STR + ks * 8 + tid4;
                a[mb][0] = __float_as_uint(Qs[base]);
                a[mb][1] = __float_as_uint(Qs[base + 8 * FQ_STR]);
                a[mb][2] = __float_as_uint(Qs[base + 4]);
                a[mb][3] = __float_as_uint(Qs[base + 8 * FQ_STR + 4]);
            }
            #pragma unroll
            for (int nb = 0; nb < 8; nb++) {
                unsigned bf[2];
                const int bbase = (nb * 8 + gid) * FK_STR + ks * 8 + tid4;
                bf[0] = __float_as_uint(Ks[bbase]);
                bf[1] = __float_as_uint(Ks[bbase + 4]);
                mma_tf32(S[0][nb], a[0], bf);
                mma_tf32(S[1][nb], a[1], bf);
            }
        }
        __syncthreads();       // all warps done reading K tile

        // prefetch next K tile (overlaps softmax + PV)
        if (t0 + 64 < SEQ) {
            #pragma unroll
            for (int i = 0; i < 8; i++) {
                const int idx = tid + i * 128;
                const int r = idx >> 4, c = idx & 15;
                cp_async16(Ks + r * FK_STR + c * 4,
                           Kp + (size_t)(t0 + 64 + r) * HDIM + c * 4);
            }
            cp_commit();
        }

        // ---- scale + mask(bits) + online softmax (registers) ----
        #pragma unroll
        for (int mb = 0; mb < 2; mb++) {
            #pragma unroll
            for (int h = 0; h < 2; h++) {
                const unsigned long long m64 = mbits[mb][h];
                float sv[8][2];
                float lm = -1e30f;
                #pragma unroll
                for (int nb = 0; nb < 8; nb++) {
                    const int pos = nb * 8 + 2 * tid4;
                    const float a0 = ((m64 >> pos) & 1ULL) ? 0.0f : -10000.0f;
                    const float a1 = ((m64 >> (pos + 1)) & 1ULL) ? 0.0f : -10000.0f;
                    const float s0 = fmaf(S[mb][nb][2 * h],     0.125f, a0);
                    const float s1 = fmaf(S[mb][nb][2 * h + 1], 0.125f, a1);
                    sv[nb][0] = s0; sv[nb][1] = s1;
                    lm = fmaxf(lm, fmaxf(s0, s1));
                }
                lm = fmaxf(lm, __shfl_xor_sync(0xffffffffu, lm, 1));
                lm = fmaxf(lm, __shfl_xor_sync(0xffffffffu, lm, 2));
                const float mo = mrow[mb][h];
                const float mn = fmaxf(mo, lm);
                const float al = __expf(mo - mn);
                mrow[mb][h] = mn;
                float ls = 0.0f;
                #pragma unroll
                for (int nb = 0; nb < 8; nb++) {
                    const float p0 = __expf(sv[nb][0] - mn);
                    const float p1 = __expf(sv[nb][1] - mn);
                    ls += p0 + p1;
                    S[mb][nb][2 * h] = p0;
                    S[mb][nb][2 * h + 1] = p1;
                }
                ls += __shfl_xor_sync(0xffffffffu, ls, 1);
                ls += __shfl_xor_sync(0xffffffffu, ls, 2);
                lrow[mb][h] = lrow[mb][h] * al + ls;
                #pragma unroll
                for (int nb = 0; nb < 8; nb++) {
                    O[mb][nb][2 * h]     *= al;
                    O[mb][nb][2 * h + 1] *= al;
                }
            }
        }

        // wait for V(t); pending afterwards: only K(t+1) (if any)
        if (t0 + 64 < SEQ) cp_wait<1>(); else cp_wait<0>();
        __syncthreads();

        // ---- O += P @ V : shuffle-transpose P C-frag -> A-frag ----
        const int src0 = (lane & 28) | (tid4 >> 1);
        const int src1 = src0 + 2;
        const bool odd = (tid4 & 1);
        #pragma unroll
        for (int kt = 0; kt < 8; kt++) {
            unsigned a[2][4];
            #pragma unroll
            for (int mb = 0; mb < 2; mb++) {
                float e0 = __shfl_sync(0xffffffffu, S[mb][kt][0], src0);
                float o0 = __shfl_sync(0xffffffffu, S[mb][kt][1], src0);
                float e1 = __shfl_sync(0xffffffffu, S[mb][kt][0], src1);
                float o1 = __shfl_sync(0xffffffffu, S[mb][kt][1], src1);
                float e2 = __shfl_sync(0xffffffffu, S[mb][kt][2], src0);
                float o2 = __shfl_sync(0xffffffffu, S[mb][kt][3], src0);
                float e3 = __shfl_sync(0xffffffffu, S[mb][kt][2], src1);
                float o3 = __shfl_sync(0xffffffffu, S[mb][kt][3], src1);
                a[mb][0] = f2tf(odd ? o0 : e0);
                a[mb][1] = f2tf(odd ? o2 : e2);
                a[mb][2] = f2tf(odd ? o1 : e1);
                a[mb][3] = f2tf(odd ? o3 : e3);
            }
            #pragma unroll
            for (int nb = 0; nb < 8; nb++) {
                unsigned bf[2];
                const int vbase = (kt * 8 + tid4) * FV_STR + nb * 8 + gid;
                bf[0] = __float_as_uint(Vs[vbase]);
                bf[1] = __float_as_uint(Vs[vbase + 4 * FV_STR]);
                mma_tf32(O[0][nb], a[0], bf);
                mma_tf32(O[1][nb], a[1], bf);
            }
        }
        __syncthreads();       // all warps done reading V tile

        // prefetch next V tile (overlaps next QK)
        if (t0 + 64 < SEQ) {
            #pragma unroll
            for (int i = 0; i < 8; i++) {
                const int idx = tid + i * 128;
                const int r = idx >> 4, c = idx & 15;
                cp_async16(Vs + r * FV_STR + c * 4,
                           Vp + (size_t)(t0 + 64 + r) * HDIM + c * 4);
            }
            cp_commit();
        }
    }

    // ---- epilogue: normalize and store ----
    #pragma unroll
    for (int mb = 0; mb < 2; mb++) {
        #pragma unroll
        for (int h = 0; h < 2; h++) {
            const float linv = 1.0f / lrow[mb][h];
            const int rg = f0 + w * 32 + mb * 16 + gid + 8 * h;
            float* op = out + ((size_t)b * SEQ + rg) * HIDDEN + nh * HDIM;
            #pragma unroll
            for (int nb = 0; nb < 8; nb++) {
                float2 v;
                v.x = O[mb][nb][2 * h] * linv;
                v.y = O[mb][nb][2 * h + 1] * linv;
                *(float2*)(op + nb * 8 + 2 * tid4) = v;
            }
        }
    }
}

// ---------------------------------------------------------------------------
// kernel_launch
// ---------------------------------------------------------------------------
extern "C" void kernel_launch(void* const* d_in, const int* in_sizes, int n_in,
                              void* d_out, int out_size)
{
    (void)in_sizes; (void)n_in; (void)out_size;

    const float* from_t = (const float*)d_in[0];
    const float* to_t   = (const float*)d_in[1];
    const int*   msk    = (const int*)d_in[2];
    const float* Wq     = (const float*)d_in[3];
    const float* bq     = (const float*)d_in[4];
    const float* Wk     = (const float*)d_in[5];
    const float* bk     = (const float*)d_in[6];
    const float* Wv     = (const float*)d_in[7];
    const float* bv     = (const float*)d_in[8];
    float* out = (float*)d_out;

    float *qp, *kp, *vp; unsigned* mb;
    cudaGetSymbolAddress((void**)&qp, g_Qs);
    cudaGetSymbolAddress((void**)&kp, g_Ks);
    cudaGetSymbolAddress((void**)&vp, g_Vs);
    cudaGetSymbolAddress((void**)&mb, g_Mbits);

    cudaFuncSetAttribute(gemm_mma_kernel,
                         cudaFuncAttributeMaxDynamicSharedMemorySize, GEMM_SMEM);
    cudaFuncSetAttribute(flash_mma_kernel,
                         cudaFuncAttributeMaxDynamicSharedMemorySize, ATT_SMEM);

    // pack mask to bits (independent of GEMM outputs)
    mask_bits_kernel<<<(MROWS * 32 + 255) / 256, 256>>>(msk, mb);

    dim3 gg(HIDDEN / 128, MROWS / 128, 3);   // (8, 32, 3)
    gemm_mma_kernel<<<gg, 256, GEMM_SMEM>>>(from_t, to_t, Wq, bq, Wk, bk,
                                            Wv, bv, qp, kp, vp);

    dim3 gf(SEQ / 128, BATCH * NHEADS);      // (16, 32)
    flash_mma_kernel<<<gf, 128, ATT_SMEM>>>(qp, kp, vp, mb, out);
}